// round 1
// baseline (speedup 1.0000x reference)
#include <cuda_runtime.h>
#include <cuda_bf16.h>

// WTA2D: per (B,C) row of H*W=3136 fp32 values, find the 313th-largest value t,
// out = (t > x) ? x : 0.
//
// One CTA per row. Row lives in registers (16 keys/thread via float4).
// Exact selection by atomic-free nibble radix-select (ballot/shuffle reductions),
// finishing tail bits with a single-warp ballot bisection over <=32 candidates.

#define NROW_ELEMS 3136
#define NVEC 784          // 3136 / 4
#define KSEL 313u

// monotonic float -> uint key (ascending): no NaNs in input
__device__ __forceinline__ unsigned f2k(float f) {
    unsigned u = __float_as_uint(f);
    return (u & 0x80000000u) ? ~u : (u | 0x80000000u);
}
__device__ __forceinline__ float k2f(unsigned k) {
    unsigned u = (k & 0x80000000u) ? (k ^ 0x80000000u) : ~k;
    return __uint_as_float(u);
}

__global__ void __launch_bounds__(256)
wta2d_kernel(const float* __restrict__ x, float* __restrict__ out) {
    const int tid  = threadIdx.x;
    const int lane = tid & 31;
    const int warp = tid >> 5;
    const size_t base = (size_t)blockIdx.x * NROW_ELEMS;

    __shared__ uint4 wsum[8][4];           // [warp][8-lane group] -> 16 byte-packed bucket counts
    __shared__ unsigned sb_prefix, sb_rank, sb_m;
    __shared__ unsigned gbuf[32];
    __shared__ int gcount;
    __shared__ unsigned sb_tkey;

    // ---- load row: 784 float4, thread p = tid + s*256 (s=3 only for tid<16) ----
    unsigned key[16];
    const bool has4 = (tid < 16);
    const float4* xin = reinterpret_cast<const float4*>(x + base);
#pragma unroll
    for (int s = 0; s < 4; ++s) {
        int p = tid + s * 256;
        if (s < 3 || has4) {
            float4 f = xin[p];
            key[4*s+0] = f2k(f.x);
            key[4*s+1] = f2k(f.y);
            key[4*s+2] = f2k(f.z);
            key[4*s+3] = f2k(f.w);
        } else {
            key[4*s+0] = 0u; key[4*s+1] = 0u; key[4*s+2] = 0u; key[4*s+3] = 0u;
        }
    }

    // ---- nibble radix-select, MSB first: find 313th-largest key ----
    unsigned prefix = 0, rank = KSEL, m = NROW_ELEMS;
    int shift = 28;

    for (int round = 0; round < 8; ++round) {
        // candidates: (key >> (shift+4)) == prefix, done as masked xor (round 0: mask = 0)
        unsigned maskTop   = ~((2u << (shift + 3)) - 1u);              // high (32-shift-4) bits
        unsigned prefixTop = prefix << ((shift + 4) & 31);             // prefix==0 when shift==28

        unsigned long long acc0 = 0ull, acc1 = 0ull;                   // 16 x 4-bit counts each half
#pragma unroll
        for (int j = 0; j < 16; ++j) {
            unsigned k = key[j];
            bool valid = (j < 12) || has4;
            bool match = valid && (((k ^ prefixTop) & maskTop) == 0u);
            unsigned d = (k >> shift) & 15u;
            unsigned long long inc = 1ull << (d * 4);
            if (j < 8) { if (match) acc0 += inc; }
            else       { if (match) acc1 += inc; }
        }
        // expand nibbles (<=8) to bytes (<=16)
        unsigned lo0 = (unsigned)acc0, hi0 = (unsigned)(acc0 >> 32);
        unsigned lo1 = (unsigned)acc1, hi1 = (unsigned)(acc1 >> 32);
        unsigned r0 = (lo0 & 0x0F0F0F0Fu)        + (lo1 & 0x0F0F0F0Fu);         // buckets 0,2,4,6
        unsigned r1 = ((lo0 >> 4) & 0x0F0F0F0Fu) + ((lo1 >> 4) & 0x0F0F0F0Fu);  // buckets 1,3,5,7
        unsigned r2 = (hi0 & 0x0F0F0F0Fu)        + (hi1 & 0x0F0F0F0Fu);         // buckets 8,10,12,14
        unsigned r3 = ((hi0 >> 4) & 0x0F0F0F0Fu) + ((hi1 >> 4) & 0x0F0F0F0Fu);  // buckets 9,11,13,15
        // 8-lane group reduce (byte fields <= 128, no overflow)
#pragma unroll
        for (int off = 1; off <= 4; off <<= 1) {
            r0 += __shfl_xor_sync(0xFFFFFFFFu, r0, off);
            r1 += __shfl_xor_sync(0xFFFFFFFFu, r1, off);
            r2 += __shfl_xor_sync(0xFFFFFFFFu, r2, off);
            r3 += __shfl_xor_sync(0xFFFFFFFFu, r3, off);
        }
        if ((lane & 7) == 0)
            wsum[warp][lane >> 3] = make_uint4(r0, r1, r2, r3);
        __syncthreads();

        // warp 0: combine 8 warps x 4 groups, suffix-scan 16 buckets, pick digit
        if (warp == 0) {
            unsigned cnt = 0;
            if (lane < 16) {
                int word = (lane & 1) | ((lane >> 3) << 1);  // bucket -> r0..r3
                int sh   = ((lane & 7) >> 1) * 8;            // byte within word
#pragma unroll
                for (int w = 0; w < 8; ++w) {
#pragma unroll
                    for (int g = 0; g < 4; ++g) {
                        const unsigned* ws = reinterpret_cast<const unsigned*>(&wsum[w][g]);
                        cnt += (ws[word] >> sh) & 0xFFu;
                    }
                }
            }
            // suffix-inclusive sum over buckets >= lane
            unsigned ssum = cnt;
#pragma unroll
            for (int off = 1; off <= 8; off <<= 1) {
                unsigned v = __shfl_down_sync(0xFFFFFFFFu, ssum, off);
                if (lane + off < 16) ssum += v;
            }
            if (lane < 16 && ssum >= rank && (ssum - cnt) < rank) {   // unique crossing lane
                sb_prefix = (prefix << 4) | (unsigned)lane;
                sb_rank   = rank - (ssum - cnt);
                sb_m      = cnt;
            }
        }
        __syncthreads();
        prefix = sb_prefix; rank = sb_rank; m = sb_m;
        shift -= 4;
        if (m <= 32 || shift < 0) break;   // uniform across block
    }

    // ---- finish remaining bits ----
    unsigned tkey;
    int rem = shift + 4;                    // unresolved low bits
    if (rem > 0) {
        if (tid == 0) gcount = 0;
        __syncthreads();
#pragma unroll
        for (int j = 0; j < 16; ++j) {
            bool valid = (j < 12) || has4;
            if (valid && ((key[j] >> rem) == prefix)) {
                int pos = atomicAdd(&gcount, 1);
                if (pos < 32) gbuf[pos] = key[j];
            }
        }
        __syncthreads();
        if (warp == 0) {
            int n = gcount; if (n > 32) n = 32;
            unsigned ck = (lane < n) ? gbuf[lane] : 0u;
            bool alive = (lane < n);
            unsigned r = rank;
            unsigned tk = prefix << rem;    // rem <= 28 here
            for (int b = rem - 1; b >= 0; --b) {
                bool bit = ((ck >> b) & 1u) != 0u;
                unsigned bal = __ballot_sync(0xFFFFFFFFu, alive && bit);
                unsigned c = __popc(bal);
                if (c >= r) { alive = alive && bit; tk |= (1u << b); }
                else        { r -= c; alive = alive && !bit; }
            }
            if (lane == 0) sb_tkey = tk;
        }
        __syncthreads();
        tkey = sb_tkey;
    } else {
        tkey = prefix;                      // all 32 bits resolved
    }

    // ---- apply mask and store (key < tkey  <=>  x < t) ----
    float4* po = reinterpret_cast<float4*>(out + base);
#pragma unroll
    for (int s = 0; s < 4; ++s) {
        int p = tid + s * 256;
        if (s < 3 || has4) {
            float4 o;
            o.x = (key[4*s+0] < tkey) ? k2f(key[4*s+0]) : 0.0f;
            o.y = (key[4*s+1] < tkey) ? k2f(key[4*s+1]) : 0.0f;
            o.z = (key[4*s+2] < tkey) ? k2f(key[4*s+2]) : 0.0f;
            o.w = (key[4*s+3] < tkey) ? k2f(key[4*s+3]) : 0.0f;
            po[p] = o;
        }
    }
}

extern "C" void kernel_launch(void* const* d_in, const int* in_sizes, int n_in,
                              void* d_out, int out_size) {
    const float* x = (const float*)d_in[0];
    float* out = (float*)d_out;
    int rows = in_sizes[0] / NROW_ELEMS;   // 64*256 = 16384
    wta2d_kernel<<<rows, 256>>>(x, out);
}